// round 4
// baseline (speedup 1.0000x reference)
#include <cuda_runtime.h>
#include <math.h>

// ---------------------------------------------------------------------------
// TinyRecursiveVerifier: 32-step recursive MLP block with convergence masking.
//   B=4096, D=512, H=2048 (derived from in_sizes at launch).
//   Per step: LN1 -> GEMM(D,H)+GELU -> GEMM(H,D) -> LN2 -> GEMM(D,H)+GELU
//             -> GEMM(H,D)=delta -> row-norm convergence update.
//   Output: concat(logits[B], converged_mask[B] as 0/1 float, z_t[B*D]).
//
// GEMMs run fp32 via Blackwell packed fma.rn.f32x2 (2 FMAs per issue slot,
// rounding identical to scalar FFMA). A operand is duplicated in SMEM so the
// (a,a) pair needed by f32x2 comes from a single LDS.128; B pairs are native.
// ---------------------------------------------------------------------------

#define MAXB 4096
#define MAXD 512
#define MAXH 2048
#define NSTEPS 32

// Scratch (allowed: __device__ globals, no runtime allocation)
__device__ float    g_z[MAXB * MAXD];   // current z_t
__device__ float    g_x[MAXB * MAXD];   // LN output (x / x2)
__device__ float    g_u[MAXB * MAXD];   // u and delta
__device__ float    g_h[MAXB * MAXH];   // hidden h1 / h2
__device__ unsigned g_mask[MAXB];       // converged mask

typedef unsigned long long ull;

__device__ __forceinline__ void fma2(ull& d, ull a, ull b) {
    // packed f32x2 FMA: d.lo += a.lo*b.lo ; d.hi += a.hi*b.hi (rn)
    asm("fma.rn.f32x2 %0, %1, %2, %0;" : "+l"(d) : "l"(a), "l"(b));
}
__device__ __forceinline__ float2 unpack2(ull u) {
    float2 f;
    asm("mov.b64 {%0, %1}, %2;" : "=f"(f.x), "=f"(f.y) : "l"(u));
    return f;
}
__device__ __forceinline__ float gelu_f(float x) {
    // exact gelu (approximate=False): x * 0.5 * (1 + erf(x/sqrt(2)))
    return 0.5f * x * (1.0f + erff(x * 0.70710678118654752440f));
}

// ---------------------------------------------------------------------------
// GEMM: C[M,N] = epi(A[M,K] @ W[K,N] + bias), row-major everything.
// BM=128, BK=16. BN/TN: (128,8) for N=2048 GEMMs, (64,4) for N=512 GEMMs.
// 256 threads, each computes 8 x TN outputs. Accumulators are f32x2 pairs
// along N. A is stored duplicated+transposed in SMEM: Asd[k][2m]=Asd[k][2m+1].
// ---------------------------------------------------------------------------
template <int BN, int TN, int DOGELU>
__global__ __launch_bounds__(256, 2)
void gemm_kernel(const float* __restrict__ A, const float* __restrict__ W,
                 const float* __restrict__ bias, float* __restrict__ C,
                 int M, int N, int K)
{
    const int BK = 16;
    __shared__ __align__(16) float Asd[BK][256];   // 128 rows duplicated
    __shared__ __align__(16) float Bs[BK][BN];

    const int tid = threadIdx.x;
    const int tx = tid & 15;          // 16 column groups
    const int ty = tid >> 4;          // 16 row groups (8 rows each)
    const int m0 = blockIdx.y * 128;
    const int n0 = blockIdx.x * BN;

    ull acc[8][TN / 2];
#pragma unroll
    for (int i = 0; i < 8; i++)
#pragma unroll
        for (int j = 0; j < TN / 2; j++) acc[i][j] = 0ull;

    for (int k0 = 0; k0 < K; k0 += BK) {
        // --- load A tile (128 x 16), store transposed + duplicated ---
#pragma unroll
        for (int it = 0; it < 2; it++) {
            int slot = tid + it * 256;            // 0..511 float4 slots
            int m    = slot >> 2;                 // 0..127
            int kk   = (slot & 3) << 2;           // 0,4,8,12
            float4 v = *(const float4*)(A + (size_t)(m0 + m) * K + k0 + kk);
            Asd[kk + 0][2 * m] = v.x; Asd[kk + 0][2 * m + 1] = v.x;
            Asd[kk + 1][2 * m] = v.y; Asd[kk + 1][2 * m + 1] = v.y;
            Asd[kk + 2][2 * m] = v.z; Asd[kk + 2][2 * m + 1] = v.z;
            Asd[kk + 3][2 * m] = v.w; Asd[kk + 3][2 * m + 1] = v.w;
        }
        // --- load B tile (16 x BN) ---
#pragma unroll
        for (int it = 0; it < (BK * BN / 4) / 256; it++) {
            int slot = tid + it * 256;
            int kk   = slot / (BN / 4);
            int nn   = (slot % (BN / 4)) << 2;
            *(float4*)(&Bs[kk][nn]) =
                *(const float4*)(W + (size_t)(k0 + kk) * N + n0 + nn);
        }
        __syncthreads();

#pragma unroll
        for (int k = 0; k < BK; k++) {
            ulonglong2 av[4];
            const ulonglong2* ap = (const ulonglong2*)(&Asd[k][ty * 16]);
#pragma unroll
            for (int t = 0; t < 4; t++) av[t] = ap[t];
            ulonglong2 bv[TN / 4];
            const ulonglong2* bp = (const ulonglong2*)(&Bs[k][tx * TN]);
#pragma unroll
            for (int t = 0; t < TN / 4; t++) bv[t] = bp[t];
#pragma unroll
            for (int i = 0; i < 8; i++) {
                ull ai = (i & 1) ? av[i >> 1].y : av[i >> 1].x;  // (a,a)
#pragma unroll
                for (int j = 0; j < TN / 2; j++) {
                    ull bj = (j & 1) ? bv[j >> 1].y : bv[j >> 1].x;
                    fma2(acc[i][j], ai, bj);
                }
            }
        }
        __syncthreads();
    }

    // --- epilogue: bias (+ optional exact gelu) ---
#pragma unroll
    for (int i = 0; i < 8; i++) {
        int row = m0 + ty * 8 + i;
#pragma unroll
        for (int j = 0; j < TN / 2; j++) {
            int col  = n0 + tx * TN + 2 * j;
            float2 v = unpack2(acc[i][j]);
            float r0 = v.x + bias[col];
            float r1 = v.y + bias[col + 1];
            if (DOGELU) { r0 = gelu_f(r0); r1 = gelu_f(r1); }
            float2 o; o.x = r0; o.y = r1;
            *(float2*)(C + (size_t)row * N + col) = o;
        }
    }
}

// ---------------------------------------------------------------------------
// LayerNorm: one block (D/4 = 128 threads) per row; two-pass mean/var
// (matches jnp.var, population variance), eps = 1e-5.
// ---------------------------------------------------------------------------
__global__ void ln_kernel(const float* __restrict__ in, const float* __restrict__ gam,
                          const float* __restrict__ bet, float* __restrict__ out, int D)
{
    int row = blockIdx.x, tid = threadIdx.x;
    __shared__ float r1[4], r2[4];
    size_t base = (size_t)row * D + tid * 4;
    const float4 v = *(const float4*)(in + base);
    float s = v.x + v.y + v.z + v.w;
#pragma unroll
    for (int o = 16; o > 0; o >>= 1) s += __shfl_xor_sync(0xffffffffu, s, o);
    if ((tid & 31) == 0) r1[tid >> 5] = s;
    __syncthreads();
    float mean = (r1[0] + r1[1] + r1[2] + r1[3]) / (float)D;

    float dx = v.x - mean, dy = v.y - mean, dz = v.z - mean, dw = v.w - mean;
    float q = dx * dx + dy * dy + dz * dz + dw * dw;
#pragma unroll
    for (int o = 16; o > 0; o >>= 1) q += __shfl_xor_sync(0xffffffffu, q, o);
    if ((tid & 31) == 0) r2[tid >> 5] = q;
    __syncthreads();
    float var  = (r2[0] + r2[1] + r2[2] + r2[3]) / (float)D;
    float rstd = rsqrtf(var + 1e-5f);

    float4 g4 = *(const float4*)(gam + tid * 4);
    float4 b4 = *(const float4*)(bet + tid * 4);
    float4 o;
    o.x = dx * rstd * g4.x + b4.x;
    o.y = dy * rstd * g4.y + b4.y;
    o.z = dz * rstd * g4.z + b4.z;
    o.w = dw * rstd * g4.w + b4.w;
    *(float4*)(out + base) = o;
}

// ---------------------------------------------------------------------------
// Convergence update: delta in g_u. dist = ||delta||2;
// mask |= dist < 0.01; z += delta only for rows still not (newly) converged.
// ---------------------------------------------------------------------------
__global__ void update_kernel(int D)
{
    int row = blockIdx.x, tid = threadIdx.x;
    __shared__ float red[4];
    size_t base = (size_t)row * D + tid * 4;
    float4 d = *(const float4*)(g_u + base);
    float q = d.x * d.x + d.y * d.y + d.z * d.z + d.w * d.w;
#pragma unroll
    for (int o = 16; o > 0; o >>= 1) q += __shfl_xor_sync(0xffffffffu, q, o);
    if ((tid & 31) == 0) red[tid >> 5] = q;
    __syncthreads();
    float ss = red[0] + red[1] + red[2] + red[3];

    unsigned conv = (g_mask[row] != 0u) || (sqrtf(ss) < 0.01f);
    if (!conv) {
        float4 z = *(const float4*)(g_z + base);
        z.x += d.x; z.y += d.y; z.z += d.z; z.w += d.w;
        *(float4*)(g_z + base) = z;
    }
    if (tid == 0) g_mask[row] = conv ? 1u : 0u;
}

// ---------------------------------------------------------------------------
// Init: copy z_init into g_z, zero the mask.
// ---------------------------------------------------------------------------
__global__ void init_kernel(const float* __restrict__ z0, int n, int Bn)
{
    int i = blockIdx.x * blockDim.x + threadIdx.x;
    if (i < n)  g_z[i]    = z0[i];
    if (i < Bn) g_mask[i] = 0u;
}

// ---------------------------------------------------------------------------
// Final: logits = z @ clf_w + clf_b; write concat(logits, mask01, z).
// Layout chosen by out_size to be robust to harness flattening conventions.
// ---------------------------------------------------------------------------
__global__ void final_kernel(const float* __restrict__ cw, const float* __restrict__ cb,
                             float* __restrict__ out, int B, int D, int out_size)
{
    int row = blockIdx.x, tid = threadIdx.x;
    __shared__ float red[4];
    size_t base = (size_t)row * D + tid * 4;
    float4 z = *(const float4*)(g_z + base);
    float4 w = *(const float4*)(cw + tid * 4);
    float s = z.x * w.x + z.y * w.y + z.z * w.z + z.w * w.w;
#pragma unroll
    for (int o = 16; o > 0; o >>= 1) s += __shfl_xor_sync(0xffffffffu, s, o);
    if ((tid & 31) == 0) red[tid >> 5] = s;
    __syncthreads();
    float logit = red[0] + red[1] + red[2] + red[3] + cb[0];

    int full = 2 * B + B * D;
    if (out_size >= full) {
        if (tid == 0) {
            out[row]     = logit;
            out[B + row] = g_mask[row] ? 1.0f : 0.0f;
        }
        *(float4*)(out + 2 * B + base) = z;
        // defensive: zero any tail beyond the expected layout
        if (out_size > full) {
            for (int i = row * blockDim.x + tid; i < out_size - full;
                 i += gridDim.x * blockDim.x)
                out[full + i] = 0.0f;
        }
    } else if (out_size == B + B * D) {
        if (tid == 0) out[row] = logit;
        *(float4*)(out + B + base) = z;
    } else if (out_size == B * D) {
        *(float4*)(out + base) = z;
    } else {
        if (tid == 0 && row < out_size) out[row] = logit;
    }
}

// ---------------------------------------------------------------------------
// kernel_launch: graph-capturable sequence of plain kernel launches.
// ---------------------------------------------------------------------------
extern "C" void kernel_launch(void* const* d_in, const int* in_sizes, int n_in,
                              void* d_out, int out_size)
{
    const float* z0   = (const float*)d_in[0];
    const float* ln1g = (const float*)d_in[1];
    const float* ln1b = (const float*)d_in[2];
    const float* w1   = (const float*)d_in[3];
    const float* b1   = (const float*)d_in[4];
    const float* w2   = (const float*)d_in[5];
    const float* b2   = (const float*)d_in[6];
    const float* ln2g = (const float*)d_in[7];
    const float* ln2b = (const float*)d_in[8];
    const float* w3   = (const float*)d_in[9];
    const float* b3   = (const float*)d_in[10];
    const float* w4   = (const float*)d_in[11];
    const float* b4   = (const float*)d_in[12];
    const float* cw   = (const float*)d_in[13];
    const float* cb   = (const float*)d_in[14];

    int D = in_sizes[1];          // 512
    int H = in_sizes[4];          // 2048
    int B = in_sizes[0] / D;      // 4096

    float* pz; float* px; float* pu; float* ph;
    cudaGetSymbolAddress((void**)&pz, g_z);
    cudaGetSymbolAddress((void**)&px, g_x);
    cudaGetSymbolAddress((void**)&pu, g_u);
    cudaGetSymbolAddress((void**)&ph, g_h);

    int n = B * D;
    init_kernel<<<(n + 255) / 256, 256>>>(z0, n, B);

    dim3 gridH(H / 128, B / 128);   // 16 x 32 = 512 blocks
    dim3 gridD(D / 64,  B / 128);   //  8 x 32 = 256 blocks
    int  lnThreads = D / 4;         // 128

    for (int step = 0; step < NSTEPS; step++) {
        ln_kernel<<<B, lnThreads>>>(pz, ln1g, ln1b, px, D);
        gemm_kernel<128, 8, 1><<<gridH, 256>>>(px, w1, b1, ph, B, H, D);
        gemm_kernel<64, 4, 0><<<gridD, 256>>>(ph, w2, b2, pu, B, D, H);
        ln_kernel<<<B, lnThreads>>>(pu, ln2g, ln2b, px, D);
        gemm_kernel<128, 8, 1><<<gridH, 256>>>(px, w3, b3, ph, B, H, D);
        gemm_kernel<64, 4, 0><<<gridD, 256>>>(ph, w4, b4, pu, B, D, H);
        update_kernel<<<B, lnThreads>>>(D);
    }

    final_kernel<<<B, lnThreads>>>(cw, cb, (float*)d_out, B, D, out_size);
}

// round 5
// speedup vs baseline: 1.0012x; 1.0012x over previous
#include <cuda_runtime.h>
#include <math.h>

// ---------------------------------------------------------------------------
// TinyRecursiveVerifier: 32-step recursive MLP block with convergence masking.
//   B=4096, D=512, H=2048 (derived from in_sizes at launch).
//   Per step: LN1 -> GEMM(D,H)+GELU -> GEMM(H,D) -> LN2 -> GEMM(D,H)+GELU
//             -> GEMM(H,D)=delta -> row-norm convergence update.
//   Output: concat(logits[B], converged_mask[B] as 0/1 float, z_t[B*D]).
//
// GEMMs run fp32 via Blackwell packed fma.rn.f32x2 (2 FMAs per issue slot,
// rounding identical to scalar FFMA). A operand is duplicated in SMEM so the
// (a,a) pair needed by f32x2 comes from a single LDS.128; B pairs are native.
// ---------------------------------------------------------------------------

#define MAXB 4096
#define MAXD 512
#define MAXH 2048
#define NSTEPS 32

// Scratch (allowed: __device__ globals, no runtime allocation)
__device__ float    g_z[MAXB * MAXD];   // current z_t
__device__ float    g_x[MAXB * MAXD];   // LN output (x / x2)
__device__ float    g_u[MAXB * MAXD];   // u and delta
__device__ float    g_h[MAXB * MAXH];   // hidden h1 / h2
__device__ unsigned g_mask[MAXB];       // converged mask

typedef unsigned long long ull;

__device__ __forceinline__ void fma2(ull& d, ull a, ull b) {
    // packed f32x2 FMA: d.lo += a.lo*b.lo ; d.hi += a.hi*b.hi (rn)
    asm("fma.rn.f32x2 %0, %1, %2, %0;" : "+l"(d) : "l"(a), "l"(b));
}
__device__ __forceinline__ float2 unpack2(ull u) {
    float2 f;
    asm("mov.b64 {%0, %1}, %2;" : "=f"(f.x), "=f"(f.y) : "l"(u));
    return f;
}
__device__ __forceinline__ float gelu_f(float x) {
    // exact gelu (approximate=False): x * 0.5 * (1 + erf(x/sqrt(2)))
    return 0.5f * x * (1.0f + erff(x * 0.70710678118654752440f));
}

// ---------------------------------------------------------------------------
// GEMM: C[M,N] = epi(A[M,K] @ W[K,N] + bias), row-major everything.
// BM=128, BK=16. BN/TN: (128,8) for N=2048 GEMMs, (64,4) for N=512 GEMMs.
// 256 threads, each computes 8 x TN outputs. Accumulators are f32x2 pairs
// along N. A is stored duplicated+transposed in SMEM: Asd[k][2m]=Asd[k][2m+1].
// ---------------------------------------------------------------------------
template <int BN, int TN, int DOGELU>
__global__ __launch_bounds__(256, 2)
void gemm_kernel(const float* __restrict__ A, const float* __restrict__ W,
                 const float* __restrict__ bias, float* __restrict__ C,
                 int M, int N, int K)
{
    const int BK = 16;
    __shared__ __align__(16) float Asd[BK][256];   // 128 rows duplicated
    __shared__ __align__(16) float Bs[BK][BN];

    const int tid = threadIdx.x;
    const int tx = tid & 15;          // 16 column groups
    const int ty = tid >> 4;          // 16 row groups (8 rows each)
    const int m0 = blockIdx.y * 128;
    const int n0 = blockIdx.x * BN;

    ull acc[8][TN / 2];
#pragma unroll
    for (int i = 0; i < 8; i++)
#pragma unroll
        for (int j = 0; j < TN / 2; j++) acc[i][j] = 0ull;

    for (int k0 = 0; k0 < K; k0 += BK) {
        // --- load A tile (128 x 16), store transposed + duplicated ---
#pragma unroll
        for (int it = 0; it < 2; it++) {
            int slot = tid + it * 256;            // 0..511 float4 slots
            int m    = slot >> 2;                 // 0..127
            int kk   = (slot & 3) << 2;           // 0,4,8,12
            float4 v = *(const float4*)(A + (size_t)(m0 + m) * K + k0 + kk);
            Asd[kk + 0][2 * m] = v.x; Asd[kk + 0][2 * m + 1] = v.x;
            Asd[kk + 1][2 * m] = v.y; Asd[kk + 1][2 * m + 1] = v.y;
            Asd[kk + 2][2 * m] = v.z; Asd[kk + 2][2 * m + 1] = v.z;
            Asd[kk + 3][2 * m] = v.w; Asd[kk + 3][2 * m + 1] = v.w;
        }
        // --- load B tile (16 x BN) ---
#pragma unroll
        for (int it = 0; it < (BK * BN / 4) / 256; it++) {
            int slot = tid + it * 256;
            int kk   = slot / (BN / 4);
            int nn   = (slot % (BN / 4)) << 2;
            *(float4*)(&Bs[kk][nn]) =
                *(const float4*)(W + (size_t)(k0 + kk) * N + n0 + nn);
        }
        __syncthreads();

#pragma unroll
        for (int k = 0; k < BK; k++) {
            ulonglong2 av[4];
            const ulonglong2* ap = (const ulonglong2*)(&Asd[k][ty * 16]);
#pragma unroll
            for (int t = 0; t < 4; t++) av[t] = ap[t];
            ulonglong2 bv[TN / 4];
            const ulonglong2* bp = (const ulonglong2*)(&Bs[k][tx * TN]);
#pragma unroll
            for (int t = 0; t < TN / 4; t++) bv[t] = bp[t];
#pragma unroll
            for (int i = 0; i < 8; i++) {
                ull ai = (i & 1) ? av[i >> 1].y : av[i >> 1].x;  // (a,a)
#pragma unroll
                for (int j = 0; j < TN / 2; j++) {
                    ull bj = (j & 1) ? bv[j >> 1].y : bv[j >> 1].x;
                    fma2(acc[i][j], ai, bj);
                }
            }
        }
        __syncthreads();
    }

    // --- epilogue: bias (+ optional exact gelu) ---
#pragma unroll
    for (int i = 0; i < 8; i++) {
        int row = m0 + ty * 8 + i;
#pragma unroll
        for (int j = 0; j < TN / 2; j++) {
            int col  = n0 + tx * TN + 2 * j;
            float2 v = unpack2(acc[i][j]);
            float r0 = v.x + bias[col];
            float r1 = v.y + bias[col + 1];
            if (DOGELU) { r0 = gelu_f(r0); r1 = gelu_f(r1); }
            float2 o; o.x = r0; o.y = r1;
            *(float2*)(C + (size_t)row * N + col) = o;
        }
    }
}

// ---------------------------------------------------------------------------
// LayerNorm: one block (D/4 = 128 threads) per row; two-pass mean/var
// (matches jnp.var, population variance), eps = 1e-5.
// ---------------------------------------------------------------------------
__global__ void ln_kernel(const float* __restrict__ in, const float* __restrict__ gam,
                          const float* __restrict__ bet, float* __restrict__ out, int D)
{
    int row = blockIdx.x, tid = threadIdx.x;
    __shared__ float r1[4], r2[4];
    size_t base = (size_t)row * D + tid * 4;
    const float4 v = *(const float4*)(in + base);
    float s = v.x + v.y + v.z + v.w;
#pragma unroll
    for (int o = 16; o > 0; o >>= 1) s += __shfl_xor_sync(0xffffffffu, s, o);
    if ((tid & 31) == 0) r1[tid >> 5] = s;
    __syncthreads();
    float mean = (r1[0] + r1[1] + r1[2] + r1[3]) / (float)D;

    float dx = v.x - mean, dy = v.y - mean, dz = v.z - mean, dw = v.w - mean;
    float q = dx * dx + dy * dy + dz * dz + dw * dw;
#pragma unroll
    for (int o = 16; o > 0; o >>= 1) q += __shfl_xor_sync(0xffffffffu, q, o);
    if ((tid & 31) == 0) r2[tid >> 5] = q;
    __syncthreads();
    float var  = (r2[0] + r2[1] + r2[2] + r2[3]) / (float)D;
    float rstd = rsqrtf(var + 1e-5f);

    float4 g4 = *(const float4*)(gam + tid * 4);
    float4 b4 = *(const float4*)(bet + tid * 4);
    float4 o;
    o.x = dx * rstd * g4.x + b4.x;
    o.y = dy * rstd * g4.y + b4.y;
    o.z = dz * rstd * g4.z + b4.z;
    o.w = dw * rstd * g4.w + b4.w;
    *(float4*)(out + base) = o;
}

// ---------------------------------------------------------------------------
// Convergence update: delta in g_u. dist = ||delta||2;
// mask |= dist < 0.01; z += delta only for rows still not (newly) converged.
// ---------------------------------------------------------------------------
__global__ void update_kernel(int D)
{
    int row = blockIdx.x, tid = threadIdx.x;
    __shared__ float red[4];
    size_t base = (size_t)row * D + tid * 4;
    float4 d = *(const float4*)(g_u + base);
    float q = d.x * d.x + d.y * d.y + d.z * d.z + d.w * d.w;
#pragma unroll
    for (int o = 16; o > 0; o >>= 1) q += __shfl_xor_sync(0xffffffffu, q, o);
    if ((tid & 31) == 0) red[tid >> 5] = q;
    __syncthreads();
    float ss = red[0] + red[1] + red[2] + red[3];

    unsigned conv = (g_mask[row] != 0u) || (sqrtf(ss) < 0.01f);
    if (!conv) {
        float4 z = *(const float4*)(g_z + base);
        z.x += d.x; z.y += d.y; z.z += d.z; z.w += d.w;
        *(float4*)(g_z + base) = z;
    }
    if (tid == 0) g_mask[row] = conv ? 1u : 0u;
}

// ---------------------------------------------------------------------------
// Init: copy z_init into g_z, zero the mask.
// ---------------------------------------------------------------------------
__global__ void init_kernel(const float* __restrict__ z0, int n, int Bn)
{
    int i = blockIdx.x * blockDim.x + threadIdx.x;
    if (i < n)  g_z[i]    = z0[i];
    if (i < Bn) g_mask[i] = 0u;
}

// ---------------------------------------------------------------------------
// Final: logits = z @ clf_w + clf_b; write concat(logits, mask01, z).
// Layout chosen by out_size to be robust to harness flattening conventions.
// ---------------------------------------------------------------------------
__global__ void final_kernel(const float* __restrict__ cw, const float* __restrict__ cb,
                             float* __restrict__ out, int B, int D, int out_size)
{
    int row = blockIdx.x, tid = threadIdx.x;
    __shared__ float red[4];
    size_t base = (size_t)row * D + tid * 4;
    float4 z = *(const float4*)(g_z + base);
    float4 w = *(const float4*)(cw + tid * 4);
    float s = z.x * w.x + z.y * w.y + z.z * w.z + z.w * w.w;
#pragma unroll
    for (int o = 16; o > 0; o >>= 1) s += __shfl_xor_sync(0xffffffffu, s, o);
    if ((tid & 31) == 0) red[tid >> 5] = s;
    __syncthreads();
    float logit = red[0] + red[1] + red[2] + red[3] + cb[0];

    int full = 2 * B + B * D;
    if (out_size >= full) {
        if (tid == 0) {
            out[row]     = logit;
            out[B + row] = g_mask[row] ? 1.0f : 0.0f;
        }
        *(float4*)(out + 2 * B + base) = z;
        // defensive: zero any tail beyond the expected layout
        if (out_size > full) {
            for (int i = row * blockDim.x + tid; i < out_size - full;
                 i += gridDim.x * blockDim.x)
                out[full + i] = 0.0f;
        }
    } else if (out_size == B + B * D) {
        if (tid == 0) out[row] = logit;
        *(float4*)(out + B + base) = z;
    } else if (out_size == B * D) {
        *(float4*)(out + base) = z;
    } else {
        if (tid == 0 && row < out_size) out[row] = logit;
    }
}

// ---------------------------------------------------------------------------
// kernel_launch: graph-capturable sequence of plain kernel launches.
// ---------------------------------------------------------------------------
extern "C" void kernel_launch(void* const* d_in, const int* in_sizes, int n_in,
                              void* d_out, int out_size)
{
    const float* z0   = (const float*)d_in[0];
    const float* ln1g = (const float*)d_in[1];
    const float* ln1b = (const float*)d_in[2];
    const float* w1   = (const float*)d_in[3];
    const float* b1   = (const float*)d_in[4];
    const float* w2   = (const float*)d_in[5];
    const float* b2   = (const float*)d_in[6];
    const float* ln2g = (const float*)d_in[7];
    const float* ln2b = (const float*)d_in[8];
    const float* w3   = (const float*)d_in[9];
    const float* b3   = (const float*)d_in[10];
    const float* w4   = (const float*)d_in[11];
    const float* b4   = (const float*)d_in[12];
    const float* cw   = (const float*)d_in[13];
    const float* cb   = (const float*)d_in[14];

    int D = in_sizes[1];          // 512
    int H = in_sizes[4];          // 2048
    int B = in_sizes[0] / D;      // 4096

    float* pz; float* px; float* pu; float* ph;
    cudaGetSymbolAddress((void**)&pz, g_z);
    cudaGetSymbolAddress((void**)&px, g_x);
    cudaGetSymbolAddress((void**)&pu, g_u);
    cudaGetSymbolAddress((void**)&ph, g_h);

    int n = B * D;
    init_kernel<<<(n + 255) / 256, 256>>>(z0, n, B);

    dim3 gridH(H / 128, B / 128);   // 16 x 32 = 512 blocks
    dim3 gridD(D / 64,  B / 128);   //  8 x 32 = 256 blocks
    int  lnThreads = D / 4;         // 128

    for (int step = 0; step < NSTEPS; step++) {
        ln_kernel<<<B, lnThreads>>>(pz, ln1g, ln1b, px, D);
        gemm_kernel<128, 8, 1><<<gridH, 256>>>(px, w1, b1, ph, B, H, D);
        gemm_kernel<64, 4, 0><<<gridD, 256>>>(ph, w2, b2, pu, B, D, H);
        ln_kernel<<<B, lnThreads>>>(pu, ln2g, ln2b, px, D);
        gemm_kernel<128, 8, 1><<<gridH, 256>>>(px, w3, b3, ph, B, H, D);
        gemm_kernel<64, 4, 0><<<gridD, 256>>>(ph, w4, b4, pu, B, D, H);
        update_kernel<<<B, lnThreads>>>(D);
    }

    final_kernel<<<B, lnThreads>>>(cw, cb, (float*)d_out, B, D, out_size);
}

// round 7
// speedup vs baseline: 1.3899x; 1.3883x over previous
#include <cuda_runtime.h>
#include <math.h>
#include <stdint.h>

// ---------------------------------------------------------------------------
// TinyRecursiveVerifier — 3xTF32 via baseline mma.sync (m16n8k8) tensor cores.
// (tcgen05 is unavailable: harness targets compute_103, not 103a.)
//   B=4096, D=512, H=2048. 32 steps: LN1 -> GEMM(D,H)+GELU -> GEMM(H,D) ->
//   LN2 -> GEMM(D,H)+GELU -> GEMM(H,D)=delta -> convergence update.
//   Split precision: D += Ahi*Bhi + Alo*Bhi + Ahi*Blo (fp32 accumulate),
//   per-GEMM rel err ~2^-22 (fp32-quality vs the 1e-3 gate).
// ---------------------------------------------------------------------------

#define MAXB 4096
#define MAXD 512
#define MAXH 2048
#define NSTEPS 32

__device__ float    g_z[MAXB * MAXD];
__device__ float    g_x[MAXB * MAXD];
__device__ float    g_u[MAXB * MAXD];
__device__ float    g_h[MAXB * MAXH];
__device__ unsigned g_mask[MAXB];
__device__ float    g_w1t[MAXD * MAXH];   // [N=H, K=D]
__device__ float    g_w2t[MAXH * MAXD];   // [N=D, K=H]
__device__ float    g_w3t[MAXD * MAXH];
__device__ float    g_w4t[MAXH * MAXD];

__device__ __forceinline__ float cvt_tf32(float x) {
    uint32_t r;
    asm("cvt.rna.tf32.f32 %0, %1;" : "=r"(r) : "f"(x));
    return __uint_as_float(r);
}
__device__ __forceinline__ void mma8(float* c, const uint32_t* a,
                                     uint32_t b0, uint32_t b1) {
    asm volatile(
        "mma.sync.aligned.m16n8k8.row.col.f32.tf32.tf32.f32 "
        "{%0,%1,%2,%3}, {%4,%5,%6,%7}, {%8,%9}, {%0,%1,%2,%3};"
        : "+f"(c[0]), "+f"(c[1]), "+f"(c[2]), "+f"(c[3])
        : "r"(a[0]), "r"(a[1]), "r"(a[2]), "r"(a[3]), "r"(b0), "r"(b1));
}
__device__ __forceinline__ float gelu_f(float x) {
    return 0.5f * x * (1.0f + erff(x * 0.70710678118654752440f));
}

// ---------------------------------------------------------------------------
// tgemm: C[M,N] = epi(A[M,K] @ WT[N,K]^T + bias).
// BM=128, BK=16, BN in {128,64}. 256 threads = 8 warps (2m x 4n),
// warp tile 64 x (BN/4). SMEM is fragment-major: 16B group g holds one
// thread's mma fragment -> conflict-free STS.128 (writer) + LDS.128 (reader).
// Double-buffered; next chunk's LDGs issued before current chunk's MMAs.
// ---------------------------------------------------------------------------
template <int BN, int DOGELU>
__global__ __launch_bounds__(256)
void tgemm_kernel(const float* __restrict__ A, const float* __restrict__ WT,
                  const float* __restrict__ bias, float* __restrict__ C,
                  int N, int K)
{
    constexpr int NT_TOT  = BN / 8;       // n8 tiles per block
    constexpr int NT      = NT_TOT / 4;   // n8 tiles per warp (4 n-warps)
    constexpr int MT      = 4;            // m16 tiles per warp (2 m-warps)
    constexpr int BGROUPS = BN / 32;      // B frag-groups per thread
    constexpr int OFF_ALO = 2048;         // floats
    constexpr int OFF_B   = 4096;
    constexpr int BUF     = 4096 + BN * 32;

    extern __shared__ float S[];
    const int tid  = threadIdx.x;
    const int wid  = tid >> 5;
    const int lane = tid & 31;
    const int wm   = wid >> 2;            // 0..1
    const int wn   = wid & 3;             // 0..3
    const int m0   = blockIdx.y * 128;
    const int n0   = blockIdx.x * BN;

    float acc[MT][NT][4];
#pragma unroll
    for (int i = 0; i < MT; i++)
#pragma unroll
        for (int j = 0; j < NT; j++)
#pragma unroll
            for (int t = 0; t < 4; t++) acc[i][j][t] = 0.0f;

    // per-thread frag-group coordinates (flattened group id == g)
    // A: g = kt*256 + mt*32 + lw  (kt = g>>8, mt = (g>>5)&7, lw = g&31)
    // B: g = kt*(NT_TOT*32) + nt*32 + lw
    float a_r[2][4];
    float b_r[BGROUPS][2];

    const int nchunk = K >> 4;

    // ---- prologue: load + stage chunk 0 ----
    {
        const int kb = 0;
#pragma unroll
        for (int g2 = 0; g2 < 2; g2++) {
            int g = tid + g2 * 256;
            int kt = g >> 8, mt = (g >> 5) & 7, lw = g & 31;
            const float* p = A + (size_t)(m0 + mt * 16 + (lw >> 2)) * K +
                             kb + kt * 8 + (lw & 3);
            a_r[g2][0] = p[0];
            a_r[g2][1] = p[(size_t)8 * K];
            a_r[g2][2] = p[4];
            a_r[g2][3] = p[(size_t)8 * K + 4];
        }
#pragma unroll
        for (int g2 = 0; g2 < BGROUPS; g2++) {
            int g = tid + g2 * 256;
            int kt = g / (NT_TOT * 32), rest = g % (NT_TOT * 32);
            int nt = rest >> 5, lw = rest & 31;
            const float* p = WT + (size_t)(n0 + nt * 8 + (lw >> 2)) * K +
                             kb + kt * 8 + (lw & 3);
            b_r[g2][0] = p[0];
            b_r[g2][1] = p[4];
        }
    }
    // stage chunk 0 into buffer 0
    {
        float* buf = S;
#pragma unroll
        for (int g2 = 0; g2 < 2; g2++) {
            int g = tid + g2 * 256;
            float4 hi, lo;
            hi.x = cvt_tf32(a_r[g2][0]); lo.x = cvt_tf32(a_r[g2][0] - hi.x);
            hi.y = cvt_tf32(a_r[g2][1]); lo.y = cvt_tf32(a_r[g2][1] - hi.y);
            hi.z = cvt_tf32(a_r[g2][2]); lo.z = cvt_tf32(a_r[g2][2] - hi.z);
            hi.w = cvt_tf32(a_r[g2][3]); lo.w = cvt_tf32(a_r[g2][3] - hi.w);
            *(float4*)&buf[g * 4]           = hi;
            *(float4*)&buf[OFF_ALO + g * 4] = lo;
        }
#pragma unroll
        for (int g2 = 0; g2 < BGROUPS; g2++) {
            int g = tid + g2 * 256;
            float4 v;
            v.x = cvt_tf32(b_r[g2][0]); v.z = cvt_tf32(b_r[g2][0] - v.x);
            v.y = cvt_tf32(b_r[g2][1]); v.w = cvt_tf32(b_r[g2][1] - v.y);
            *(float4*)&buf[OFF_B + g * 4] = v;
        }
    }
    __syncthreads();

    for (int ch = 0; ch < nchunk; ch++) {
        // ---- prefetch next chunk's globals (hide latency under MMAs) ----
        if (ch + 1 < nchunk) {
            const int kb = (ch + 1) << 4;
#pragma unroll
            for (int g2 = 0; g2 < 2; g2++) {
                int g = tid + g2 * 256;
                int kt = g >> 8, mt = (g >> 5) & 7, lw = g & 31;
                const float* p = A + (size_t)(m0 + mt * 16 + (lw >> 2)) * K +
                                 kb + kt * 8 + (lw & 3);
                a_r[g2][0] = p[0];
                a_r[g2][1] = p[(size_t)8 * K];
                a_r[g2][2] = p[4];
                a_r[g2][3] = p[(size_t)8 * K + 4];
            }
#pragma unroll
            for (int g2 = 0; g2 < BGROUPS; g2++) {
                int g = tid + g2 * 256;
                int kt = g / (NT_TOT * 32), rest = g % (NT_TOT * 32);
                int nt = rest >> 5, lw = rest & 31;
                const float* p = WT + (size_t)(n0 + nt * 8 + (lw >> 2)) * K +
                                 kb + kt * 8 + (lw & 3);
                b_r[g2][0] = p[0];
                b_r[g2][1] = p[4];
            }
        }

        // ---- compute current chunk ----
        {
            const float* buf = S + (ch & 1) * BUF;
            const uint32_t* Ah = (const uint32_t*)buf;
            const uint32_t* Al = (const uint32_t*)(buf + OFF_ALO);
            const uint32_t* Bf = (const uint32_t*)(buf + OFF_B);
#pragma unroll
            for (int kt = 0; kt < 2; kt++) {
                uint4 ah[MT], al[MT], bb[NT];
#pragma unroll
                for (int i = 0; i < MT; i++) {
                    int grp = (kt * 8 + wm * 4 + i) * 32 + lane;
                    ah[i] = *(const uint4*)&Ah[grp * 4];
                    al[i] = *(const uint4*)&Al[grp * 4];
                }
#pragma unroll
                for (int j = 0; j < NT; j++) {
                    int grp = (kt * NT_TOT + wn * NT + j) * 32 + lane;
                    bb[j] = *(const uint4*)&Bf[grp * 4];
                }
#pragma unroll
                for (int i = 0; i < MT; i++)
#pragma unroll
                    for (int j = 0; j < NT; j++) {
                        mma8(acc[i][j], &ah[i].x, bb[j].x, bb[j].y); // hi*hi
                        mma8(acc[i][j], &al[i].x, bb[j].x, bb[j].y); // lo*hi
                        mma8(acc[i][j], &ah[i].x, bb[j].z, bb[j].w); // hi*lo
                    }
            }
        }

        // ---- stage next chunk into the other buffer ----
        if (ch + 1 < nchunk) {
            float* buf = S + ((ch + 1) & 1) * BUF;
#pragma unroll
            for (int g2 = 0; g2 < 2; g2++) {
                int g = tid + g2 * 256;
                float4 hi, lo;
                hi.x = cvt_tf32(a_r[g2][0]); lo.x = cvt_tf32(a_r[g2][0] - hi.x);
                hi.y = cvt_tf32(a_r[g2][1]); lo.y = cvt_tf32(a_r[g2][1] - hi.y);
                hi.z = cvt_tf32(a_r[g2][2]); lo.z = cvt_tf32(a_r[g2][2] - hi.z);
                hi.w = cvt_tf32(a_r[g2][3]); lo.w = cvt_tf32(a_r[g2][3] - hi.w);
                *(float4*)&buf[g * 4]           = hi;
                *(float4*)&buf[OFF_ALO + g * 4] = lo;
            }
#pragma unroll
            for (int g2 = 0; g2 < BGROUPS; g2++) {
                int g = tid + g2 * 256;
                float4 v;
                v.x = cvt_tf32(b_r[g2][0]); v.z = cvt_tf32(b_r[g2][0] - v.x);
                v.y = cvt_tf32(b_r[g2][1]); v.w = cvt_tf32(b_r[g2][1] - v.y);
                *(float4*)&buf[OFF_B + g * 4] = v;
            }
        }
        __syncthreads();
    }

    // ---- epilogue: bias (+ optional exact gelu), coalesced float2 stores ----
    const int grp = lane >> 2, tig = lane & 3;
#pragma unroll
    for (int i = 0; i < MT; i++) {
        int row0 = m0 + wm * 64 + i * 16 + grp;
#pragma unroll
        for (int j = 0; j < NT; j++) {
            int col = n0 + wn * (BN / 4) + j * 8 + tig * 2;
            float b0 = bias[col], b1 = bias[col + 1];
            float r0 = acc[i][j][0] + b0, r1 = acc[i][j][1] + b1;
            float r2 = acc[i][j][2] + b0, r3 = acc[i][j][3] + b1;
            if (DOGELU) {
                r0 = gelu_f(r0); r1 = gelu_f(r1);
                r2 = gelu_f(r2); r3 = gelu_f(r3);
            }
            float2 lo; lo.x = r0; lo.y = r1;
            float2 hi; hi.x = r2; hi.y = r3;
            *(float2*)(C + (size_t)row0 * N + col)       = lo;
            *(float2*)(C + (size_t)(row0 + 8) * N + col) = hi;
        }
    }
}

// ---------------------------------------------------------------------------
// Weight transpose: W[K,N] -> WT[N,K] (coalesced via SMEM tile).
// ---------------------------------------------------------------------------
__global__ void transpose_kernel(const float* __restrict__ in, float* __restrict__ out,
                                 int K, int N)
{
    __shared__ float t[32][33];
    int n0 = blockIdx.x * 32, k0 = blockIdx.y * 32;
    int tx = threadIdx.x, ty = threadIdx.y;          // 32 x 8
#pragma unroll
    for (int j = 0; j < 32; j += 8)
        t[ty + j][tx] = in[(size_t)(k0 + ty + j) * N + n0 + tx];
    __syncthreads();
#pragma unroll
    for (int j = 0; j < 32; j += 8)
        out[(size_t)(n0 + ty + j) * K + k0 + tx] = t[tx][ty + j];
}

// ---------------------------------------------------------------------------
// LayerNorm (two-pass, population variance, eps=1e-5). 128 threads/row.
// ---------------------------------------------------------------------------
__global__ void ln_kernel(const float* __restrict__ in, const float* __restrict__ gam,
                          const float* __restrict__ bet, float* __restrict__ out, int D)
{
    int row = blockIdx.x, tid = threadIdx.x;
    __shared__ float r1[4], r2[4];
    size_t base = (size_t)row * D + tid * 4;
    const float4 v = *(const float4*)(in + base);
    float s = v.x + v.y + v.z + v.w;
#pragma unroll
    for (int o = 16; o > 0; o >>= 1) s += __shfl_xor_sync(0xffffffffu, s, o);
    if ((tid & 31) == 0) r1[tid >> 5] = s;
    __syncthreads();
    float mean = (r1[0] + r1[1] + r1[2] + r1[3]) / (float)D;

    float dx = v.x - mean, dy = v.y - mean, dz = v.z - mean, dw = v.w - mean;
    float q = dx * dx + dy * dy + dz * dz + dw * dw;
#pragma unroll
    for (int o = 16; o > 0; o >>= 1) q += __shfl_xor_sync(0xffffffffu, q, o);
    if ((tid & 31) == 0) r2[tid >> 5] = q;
    __syncthreads();
    float var  = (r2[0] + r2[1] + r2[2] + r2[3]) / (float)D;
    float rstd = rsqrtf(var + 1e-5f);

    float4 g4 = *(const float4*)(gam + tid * 4);
    float4 b4 = *(const float4*)(bet + tid * 4);
    float4 o;
    o.x = dx * rstd * g4.x + b4.x;
    o.y = dy * rstd * g4.y + b4.y;
    o.z = dz * rstd * g4.z + b4.z;
    o.w = dw * rstd * g4.w + b4.w;
    *(float4*)(out + base) = o;
}

// ---------------------------------------------------------------------------
// Convergence update: delta in g_u. mask |= ||delta|| < 0.01; z += delta if live.
// ---------------------------------------------------------------------------
__global__ void update_kernel(int D)
{
    int row = blockIdx.x, tid = threadIdx.x;
    __shared__ float red[4];
    size_t base = (size_t)row * D + tid * 4;
    float4 d = *(const float4*)(g_u + base);
    float q = d.x * d.x + d.y * d.y + d.z * d.z + d.w * d.w;
#pragma unroll
    for (int o = 16; o > 0; o >>= 1) q += __shfl_xor_sync(0xffffffffu, q, o);
    if ((tid & 31) == 0) red[tid >> 5] = q;
    __syncthreads();
    float ss = red[0] + red[1] + red[2] + red[3];

    unsigned conv = (g_mask[row] != 0u) || (sqrtf(ss) < 0.01f);
    if (!conv) {
        float4 z = *(const float4*)(g_z + base);
        z.x += d.x; z.y += d.y; z.z += d.z; z.w += d.w;
        *(float4*)(g_z + base) = z;
    }
    if (tid == 0) g_mask[row] = conv ? 1u : 0u;
}

__global__ void init_kernel(const float* __restrict__ z0, int n, int Bn)
{
    int i = blockIdx.x * blockDim.x + threadIdx.x;
    if (i < n)  g_z[i]    = z0[i];
    if (i < Bn) g_mask[i] = 0u;
}

__global__ void final_kernel(const float* __restrict__ cw, const float* __restrict__ cb,
                             float* __restrict__ out, int B, int D, int out_size)
{
    int row = blockIdx.x, tid = threadIdx.x;
    __shared__ float red[4];
    size_t base = (size_t)row * D + tid * 4;
    float4 z = *(const float4*)(g_z + base);
    float4 w = *(const float4*)(cw + tid * 4);
    float s = z.x * w.x + z.y * w.y + z.z * w.z + z.w * w.w;
#pragma unroll
    for (int o = 16; o > 0; o >>= 1) s += __shfl_xor_sync(0xffffffffu, s, o);
    if ((tid & 31) == 0) red[tid >> 5] = s;
    __syncthreads();
    float logit = red[0] + red[1] + red[2] + red[3] + cb[0];

    int full = 2 * B + B * D;
    if (out_size >= full) {
        if (tid == 0) {
            out[row]     = logit;
            out[B + row] = g_mask[row] ? 1.0f : 0.0f;
        }
        *(float4*)(out + 2 * B + base) = z;
        if (out_size > full) {
            for (int i = row * blockDim.x + tid; i < out_size - full;
                 i += gridDim.x * blockDim.x)
                out[full + i] = 0.0f;
        }
    } else if (out_size == B + B * D) {
        if (tid == 0) out[row] = logit;
        *(float4*)(out + B + base) = z;
    } else if (out_size == B * D) {
        *(float4*)(out + base) = z;
    } else {
        if (tid == 0 && row < out_size) out[row] = logit;
    }
}

// ---------------------------------------------------------------------------
extern "C" void kernel_launch(void* const* d_in, const int* in_sizes, int n_in,
                              void* d_out, int out_size)
{
    const float* z0   = (const float*)d_in[0];
    const float* ln1g = (const float*)d_in[1];
    const float* ln1b = (const float*)d_in[2];
    const float* w1   = (const float*)d_in[3];
    const float* b1   = (const float*)d_in[4];
    const float* w2   = (const float*)d_in[5];
    const float* b2   = (const float*)d_in[6];
    const float* ln2g = (const float*)d_in[7];
    const float* ln2b = (const float*)d_in[8];
    const float* w3   = (const float*)d_in[9];
    const float* b3   = (const float*)d_in[10];
    const float* w4   = (const float*)d_in[11];
    const float* b4   = (const float*)d_in[12];
    const float* cw   = (const float*)d_in[13];
    const float* cb   = (const float*)d_in[14];

    int D = in_sizes[1];          // 512
    int H = in_sizes[4];          // 2048
    int B = in_sizes[0] / D;      // 4096

    float *pz, *px, *pu, *ph, *pw1t, *pw2t, *pw3t, *pw4t;
    cudaGetSymbolAddress((void**)&pz, g_z);
    cudaGetSymbolAddress((void**)&px, g_x);
    cudaGetSymbolAddress((void**)&pu, g_u);
    cudaGetSymbolAddress((void**)&ph, g_h);
    cudaGetSymbolAddress((void**)&pw1t, g_w1t);
    cudaGetSymbolAddress((void**)&pw2t, g_w2t);
    cudaGetSymbolAddress((void**)&pw3t, g_w3t);
    cudaGetSymbolAddress((void**)&pw4t, g_w4t);

    const int SMEM_H = 2 * (4096 + 128 * 32) * 4;   // 65536 B
    const int SMEM_D = 2 * (4096 + 64 * 32) * 4;    // 49152 B
    cudaFuncSetAttribute(tgemm_kernel<128, 1>,
                         cudaFuncAttributeMaxDynamicSharedMemorySize, SMEM_H);
    cudaFuncSetAttribute(tgemm_kernel<64, 0>,
                         cudaFuncAttributeMaxDynamicSharedMemorySize, SMEM_D);

    // preprocessing: weights -> [N,K] transposed (inside the graph; cheap)
    dim3 tb(32, 8);
    transpose_kernel<<<dim3(H / 32, D / 32), tb>>>(w1, pw1t, D, H);
    transpose_kernel<<<dim3(D / 32, H / 32), tb>>>(w2, pw2t, H, D);
    transpose_kernel<<<dim3(H / 32, D / 32), tb>>>(w3, pw3t, D, H);
    transpose_kernel<<<dim3(D / 32, H / 32), tb>>>(w4, pw4t, H, D);

    int n = B * D;
    init_kernel<<<(n + 255) / 256, 256>>>(z0, n, B);

    dim3 gridH(H / 128, B / 128);   // 16 x 32 = 512 CTAs
    dim3 gridD(D / 64,  B / 128);   //  8 x 32 = 256 CTAs
    int  lnThreads = D / 4;         // 128

    for (int step = 0; step < NSTEPS; step++) {
        ln_kernel<<<B, lnThreads>>>(pz, ln1g, ln1b, px, D);
        tgemm_kernel<128, 1><<<gridH, 256, SMEM_H>>>(px, pw1t, b1, ph, H, D);
        tgemm_kernel<64, 0><<<gridD, 256, SMEM_D>>>(ph, pw2t, b2, pu, D, H);
        ln_kernel<<<B, lnThreads>>>(pu, ln2g, ln2b, px, D);
        tgemm_kernel<128, 1><<<gridH, 256, SMEM_H>>>(px, pw3t, b3, ph, H, D);
        tgemm_kernel<64, 0><<<gridD, 256, SMEM_D>>>(ph, pw4t, b4, pu, D, H);
        update_kernel<<<B, lnThreads>>>(D);
    }

    final_kernel<<<B, lnThreads>>>(cw, cb, (float*)d_out, B, D, out_size);
}

// round 8
// speedup vs baseline: 2.0801x; 1.4966x over previous
#include <cuda_runtime.h>
#include <math.h>
#include <stdint.h>

// ---------------------------------------------------------------------------
// TinyRecursiveVerifier — 3xTF32 mma.sync (m16n8k8) with fully pre-packed
// operands + cp.async 3-stage pipeline.
//   - Weights: split hi/lo + packed fragment-major ONCE per launch.
//   - Activations: producers (LN / GEMM1 epilogue) emit pre-split packed
//     fragments; GEMM mainloop = cp.async -> LDS.128 -> MMA only.
//   Split precision: D += Ahi*Bhi + Alo*Bhi + Ahi*Blo (fp32 accumulate).
// ---------------------------------------------------------------------------

#define MAXB 4096
#define MAXD 512
#define MAXH 2048
#define NSTEPS 32

__device__ float    g_z[MAXB * MAXD];
__device__ float    g_u[MAXB * MAXD];
__device__ float    g_xh[MAXB * MAXD];      // packed LN output hi
__device__ float    g_xl[MAXB * MAXD];      // packed LN output lo
__device__ float    g_hh[MAXB * MAXH];      // packed hidden hi
__device__ float    g_hl[MAXB * MAXH];      // packed hidden lo
__device__ unsigned g_mask[MAXB];
__device__ float    g_w1p[2 * MAXD * MAXH]; // packed weights (hi/lo interleaved)
__device__ float    g_w2p[2 * MAXH * MAXD];
__device__ float    g_w3p[2 * MAXD * MAXH];
__device__ float    g_w4p[2 * MAXH * MAXD];

__device__ __forceinline__ float cvt_tf32(float x) {
    uint32_t r;
    asm("cvt.rna.tf32.f32 %0, %1;" : "=r"(r) : "f"(x));
    return __uint_as_float(r);
}
__device__ __forceinline__ void mma8(float* c, const uint32_t* a,
                                     uint32_t b0, uint32_t b1) {
    asm volatile(
        "mma.sync.aligned.m16n8k8.row.col.f32.tf32.tf32.f32 "
        "{%0,%1,%2,%3}, {%4,%5,%6,%7}, {%8,%9}, {%0,%1,%2,%3};"
        : "+f"(c[0]), "+f"(c[1]), "+f"(c[2]), "+f"(c[3])
        : "r"(a[0]), "r"(a[1]), "r"(a[2]), "r"(a[3]), "r"(b0), "r"(b1));
}
__device__ __forceinline__ void cp16(uint32_t saddr, const void* gaddr) {
    asm volatile("cp.async.cg.shared.global [%0], [%1], 16;"
                 :: "r"(saddr), "l"(gaddr));
}
__device__ __forceinline__ float gelu_f(float x) {
    return 0.5f * x * (1.0f + erff(x * 0.70710678118654752440f));
}

// ---------------------------------------------------------------------------
// Weight pack: W[K,N] row-major -> packed fragment-major tf32 hi/lo.
// Per (nt,kt,lane): float4 {b0h, b1h, b0l, b1l}, b0 = W[kt*8+(l&3)][nt*8+(l>>2)],
// b1 = W[kt*8+(l&3)+4][same n]. Tile = 32 lanes x 16B contiguous.
// ---------------------------------------------------------------------------
__global__ void pack_w_kernel(const float* __restrict__ W, float* __restrict__ P,
                              int K, int N)
{
    int gid = blockIdx.x * 256 + threadIdx.x;
    int KT = K >> 3;
    int total = (N >> 3) * KT * 32;
    if (gid >= total) return;
    int ln   = gid & 31;
    int tile = gid >> 5;
    int kt   = tile % KT;
    int nt   = tile / KT;
    int k = kt * 8 + (ln & 3);
    int n = nt * 8 + (ln >> 2);
    float b0 = W[(size_t)k * N + n];
    float b1 = W[(size_t)(k + 4) * N + n];
    float h0 = cvt_tf32(b0), l0 = cvt_tf32(b0 - h0);
    float h1 = cvt_tf32(b1), l1 = cvt_tf32(b1 - h1);
    float4 o; o.x = h0; o.y = h1; o.z = l0; o.w = l1;
    *(float4*)(P + (size_t)gid * 4) = o;
}

// ---------------------------------------------------------------------------
// LayerNorm + pack: 16 rows per block (one mt stripe), 512 threads
// (warp = row). Output: packed fragment-major hi/lo arrays.
// A-fragment (mt,kt,lane l): {A[r][k], A[r+8][k], A[r][k+4], A[r+8][k+4]},
// r = 16mt + (l>>2), k = 8kt + (l&3).
// ---------------------------------------------------------------------------
__global__ void ln_pack_kernel(const float* __restrict__ in,
                               const float* __restrict__ gam,
                               const float* __restrict__ bet,
                               float* __restrict__ out_hi,
                               float* __restrict__ out_lo, int D)
{
    __shared__ float y[16][516];                 // pad 4: conflict-free reads
    const int tid  = threadIdx.x;
    const int w    = tid >> 5;                   // row in stripe (0..15)
    const int lane = tid & 31;
    const int row  = blockIdx.x * 16 + w;
    const float* src = in + (size_t)row * D;
    const int J = D >> 7;                        // 4 for D=512

    float4 v[4];
    float s = 0.0f;
#pragma unroll
    for (int j = 0; j < 4; j++) {
        if (j < J) {
            v[j] = *(const float4*)(src + (lane + j * 32) * 4);
            s += v[j].x + v[j].y + v[j].z + v[j].w;
        }
    }
#pragma unroll
    for (int o = 16; o > 0; o >>= 1) s += __shfl_xor_sync(0xffffffffu, s, o);
    float mean = s / (float)D;

    float q = 0.0f;
#pragma unroll
    for (int j = 0; j < 4; j++) {
        if (j < J) {
            float a = v[j].x - mean, b = v[j].y - mean;
            float c = v[j].z - mean, d = v[j].w - mean;
            q += a * a + b * b + c * c + d * d;
        }
    }
#pragma unroll
    for (int o = 16; o > 0; o >>= 1) q += __shfl_xor_sync(0xffffffffu, q, o);
    float rstd = rsqrtf(q / (float)D + 1e-5f);

#pragma unroll
    for (int j = 0; j < 4; j++) {
        if (j < J) {
            int col = (lane + j * 32) * 4;
            float4 g4 = *(const float4*)(gam + col);
            float4 b4 = *(const float4*)(bet + col);
            float4 o;
            o.x = (v[j].x - mean) * rstd * g4.x + b4.x;
            o.y = (v[j].y - mean) * rstd * g4.y + b4.y;
            o.z = (v[j].z - mean) * rstd * g4.z + b4.z;
            o.w = (v[j].w - mean) * rstd * g4.w + b4.w;
            *(float4*)(&y[w][col]) = o;
        }
    }
    __syncthreads();

    // packed write: KT*32 units, 512 threads
    const int KT = D >> 3;
    for (int u = tid; u < KT * 32; u += 512) {
        int kt = u >> 5, ln = u & 31;
        int r = ln >> 2, kk = kt * 8 + (ln & 3);
        float a0 = y[r][kk],     a1 = y[r + 8][kk];
        float a2 = y[r][kk + 4], a3 = y[r + 8][kk + 4];
        float h0 = cvt_tf32(a0), h1 = cvt_tf32(a1);
        float h2 = cvt_tf32(a2), h3 = cvt_tf32(a3);
        float4 hi; hi.x = h0; hi.y = h1; hi.z = h2; hi.w = h3;
        float4 lo;
        lo.x = cvt_tf32(a0 - h0); lo.y = cvt_tf32(a1 - h1);
        lo.z = cvt_tf32(a2 - h2); lo.w = cvt_tf32(a3 - h3);
        size_t base = (((size_t)blockIdx.x * KT + kt) * 32 + ln) * 4;
        *(float4*)(out_hi + base) = hi;
        *(float4*)(out_lo + base) = lo;
    }
}

// ---------------------------------------------------------------------------
// tgemm: C = epi(A @ B^T + bias) with pre-packed operands.
// BM=128, BK=16, BN in {128,64}. 8 warps (2m x 4n), MT=4 m16 tiles/warp.
// 3-stage cp.async pipeline; smem fragment-major; conflict-free LDS.128.
// EPI=0: plain bias store. EPI=1: bias+gelu, shuffle-repack, packed hi/lo out.
// ---------------------------------------------------------------------------
template <int BN>
__device__ __forceinline__ void issue_chunk(
    uint32_t sb, const float* Ah, const float* Al, const float* Bp,
    int tid, int m0_16, int n0_8, int KTA, int kg0)
{
    constexpr int NT_TOT  = BN / 8;
    constexpr int OFF_ALO = 2048 * 4;   // bytes
    constexpr int OFF_B   = 4096 * 4;
#pragma unroll
    for (int g2 = 0; g2 < 2; g2++) {
        int g  = tid + g2 * 256;
        int kt = g >> 8, mt = (g >> 5) & 7, ln = g & 31;
        size_t src = (((size_t)(m0_16 + mt) * KTA + kg0 + kt) * 32 + ln) * 4;
        cp16(sb + g * 16, Ah + src);
        cp16(sb + OFF_ALO + g * 16, Al + src);
    }
#pragma unroll
    for (int g2 = 0; g2 < BN / 32; g2++) {
        int g    = tid + g2 * 256;
        int kt   = g / (NT_TOT * 32);
        int rest = g % (NT_TOT * 32);
        int nt   = rest >> 5, ln = rest & 31;
        size_t src = (((size_t)(n0_8 + nt) * KTA + kg0 + kt) * 32 + ln) * 4;
        cp16(sb + OFF_B + g * 16, Bp + src);
    }
}

template <int BN, int EPI>
__global__ __launch_bounds__(256, 2)
void tgemm_kernel(const float* __restrict__ Ah, const float* __restrict__ Al,
                  const float* __restrict__ Bp, const float* __restrict__ bias,
                  float* __restrict__ C0, float* __restrict__ C1,
                  int N, int K)
{
    constexpr int NT_TOT  = BN / 8;
    constexpr int NT      = NT_TOT / 4;
    constexpr int MT      = 4;
    constexpr int STAGES  = 3;
    constexpr int SFLOATS = 4096 + BN * 32;
    constexpr int OFF_ALO = 2048;
    constexpr int OFF_B   = 4096;

    extern __shared__ float S[];
    const int tid  = threadIdx.x;
    const int wid  = tid >> 5;
    const int lane = tid & 31;
    const int wm   = wid >> 2;
    const int wn   = wid & 3;
    const int m0   = blockIdx.y * 128;
    const int n0   = blockIdx.x * BN;
    const int m0_16 = m0 >> 4;
    const int n0_8  = n0 >> 3;
    const int KTA   = K >> 3;
    const uint32_t sb0 = (uint32_t)__cvta_generic_to_shared(S);

    float acc[MT][NT][4];
#pragma unroll
    for (int i = 0; i < MT; i++)
#pragma unroll
        for (int j = 0; j < NT; j++)
#pragma unroll
            for (int t = 0; t < 4; t++) acc[i][j][t] = 0.0f;

    const int nchunk = K >> 4;

    // prologue: stages 0..STAGES-2
#pragma unroll
    for (int s = 0; s < STAGES - 1; s++) {
        issue_chunk<BN>(sb0 + s * SFLOATS * 4, Ah, Al, Bp, tid,
                        m0_16, n0_8, KTA, s * 2);
        asm volatile("cp.async.commit_group;");
    }

    for (int ch = 0; ch < nchunk; ch++) {
        asm volatile("cp.async.wait_group %0;" :: "n"(STAGES - 2));
        __syncthreads();
        int nx = ch + STAGES - 1;
        if (nx < nchunk)
            issue_chunk<BN>(sb0 + (nx % STAGES) * SFLOATS * 4, Ah, Al, Bp, tid,
                            m0_16, n0_8, KTA, nx * 2);
        asm volatile("cp.async.commit_group;");

        const float* buf = S + (ch % STAGES) * SFLOATS;
        const uint32_t* Ahs = (const uint32_t*)buf;
        const uint32_t* Als = (const uint32_t*)(buf + OFF_ALO);
        const uint32_t* Bfs = (const uint32_t*)(buf + OFF_B);
#pragma unroll
        for (int kt = 0; kt < 2; kt++) {
            uint4 ah[MT], al[MT], bb[NT];
#pragma unroll
            for (int i = 0; i < MT; i++) {
                int grp = (kt * 8 + wm * 4 + i) * 32 + lane;
                ah[i] = *(const uint4*)&Ahs[grp * 4];
                al[i] = *(const uint4*)&Als[grp * 4];
            }
#pragma unroll
            for (int j = 0; j < NT; j++) {
                int grp = (kt * NT_TOT + wn * NT + j) * 32 + lane;
                bb[j] = *(const uint4*)&Bfs[grp * 4];
            }
#pragma unroll
            for (int i = 0; i < MT; i++)
#pragma unroll
                for (int j = 0; j < NT; j++) {
                    mma8(acc[i][j], &ah[i].x, bb[j].x, bb[j].y); // hi*hi
                    mma8(acc[i][j], &al[i].x, bb[j].x, bb[j].y); // lo*hi
                    mma8(acc[i][j], &ah[i].x, bb[j].z, bb[j].w); // hi*lo
                }
        }
    }

    // ---- epilogue ----
    if (EPI == 0) {
        const int grp = lane >> 2, tig = lane & 3;
#pragma unroll
        for (int i = 0; i < MT; i++) {
            int row0 = m0 + wm * 64 + i * 16 + grp;
#pragma unroll
            for (int j = 0; j < NT; j++) {
                int col = n0 + wn * NT * 8 + j * 8 + tig * 2;
                float b0 = bias[col], b1 = bias[col + 1];
                float2 lo2; lo2.x = acc[i][j][0] + b0; lo2.y = acc[i][j][1] + b1;
                float2 hi2; hi2.x = acc[i][j][2] + b0; hi2.y = acc[i][j][3] + b1;
                *(float2*)(C0 + (size_t)row0 * N + col)       = lo2;
                *(float2*)(C0 + (size_t)(row0 + 8) * N + col) = hi2;
            }
        }
    } else {
        // gelu + shuffle-repack into fragment-major packed hi/lo
        const int t = lane & 3;
        const int src1 = (lane & ~3) + (t >> 1);
        const int src2 = src1 + 2;
        const int KTO  = N >> 3;
#pragma unroll
        for (int i = 0; i < MT; i++) {
            int R0 = m0 + wm * 64 + i * 16;
#pragma unroll
            for (int j = 0; j < NT; j++) {
                int C0c = n0 + wn * NT * 8 + j * 8;
                float b0 = bias[C0c + 2 * t], b1 = bias[C0c + 2 * t + 1];
                float v0 = gelu_f(acc[i][j][0] + b0);
                float v1 = gelu_f(acc[i][j][1] + b1);
                float v2 = gelu_f(acc[i][j][2] + b0);
                float v3 = gelu_f(acc[i][j][3] + b1);
                float s10 = __shfl_sync(0xffffffffu, v0, src1);
                float s11 = __shfl_sync(0xffffffffu, v1, src1);
                float s20 = __shfl_sync(0xffffffffu, v0, src2);
                float s21 = __shfl_sync(0xffffffffu, v1, src2);
                float s12 = __shfl_sync(0xffffffffu, v2, src1);
                float s13 = __shfl_sync(0xffffffffu, v3, src1);
                float s22 = __shfl_sync(0xffffffffu, v2, src2);
                float s23 = __shfl_sync(0xffffffffu, v3, src2);
                float a0 = (t & 1) ? s11 : s10;   // (r, t)
                float a1 = (t & 1) ? s13 : s12;   // (r+8, t)
                float a2 = (t & 1) ? s21 : s20;   // (r, t+4)
                float a3 = (t & 1) ? s23 : s22;   // (r+8, t+4)
                float h0 = cvt_tf32(a0), h1 = cvt_tf32(a1);
                float h2 = cvt_tf32(a2), h3 = cvt_tf32(a3);
                float4 hi; hi.x = h0; hi.y = h1; hi.z = h2; hi.w = h3;
                float4 lo;
                lo.x = cvt_tf32(a0 - h0); lo.y = cvt_tf32(a1 - h1);
                lo.z = cvt_tf32(a2 - h2); lo.w = cvt_tf32(a3 - h3);
                size_t base = (((size_t)(R0 >> 4) * KTO + (C0c >> 3)) * 32 + lane) * 4;
                *(float4*)(C0 + base) = hi;
                *(float4*)(C1 + base) = lo;
            }
        }
    }
}

// ---------------------------------------------------------------------------
// Convergence update: delta in g_u. mask |= ||delta|| < 0.01; z += delta if live.
// ---------------------------------------------------------------------------
__global__ void update_kernel(int D)
{
    int row = blockIdx.x, tid = threadIdx.x;
    __shared__ float red[4];
    size_t base = (size_t)row * D + tid * 4;
    float4 d = *(const float4*)(g_u + base);
    float q = d.x * d.x + d.y * d.y + d.z * d.z + d.w * d.w;
#pragma unroll
    for (int o = 16; o > 0; o >>= 1) q += __shfl_xor_sync(0xffffffffu, q, o);
    if ((tid & 31) == 0) red[tid >> 5] = q;
    __syncthreads();
    float ss = red[0] + red[1] + red[2] + red[3];

    unsigned conv = (g_mask[row] != 0u) || (sqrtf(ss) < 0.01f);
    if (!conv) {
        float4 z = *(const float4*)(g_z + base);
        z.x += d.x; z.y += d.y; z.z += d.z; z.w += d.w;
        *(float4*)(g_z + base) = z;
    }
    if (tid == 0) g_mask[row] = conv ? 1u : 0u;
}

__global__ void init_kernel(const float* __restrict__ z0, int n, int Bn)
{
    int i = blockIdx.x * blockDim.x + threadIdx.x;
    if (i < n)  g_z[i]    = z0[i];
    if (i < Bn) g_mask[i] = 0u;
}

__global__ void final_kernel(const float* __restrict__ cw, const float* __restrict__ cb,
                             float* __restrict__ out, int B, int D, int out_size)
{
    int row = blockIdx.x, tid = threadIdx.x;
    __shared__ float red[4];
    size_t base = (size_t)row * D + tid * 4;
    float4 z = *(const float4*)(g_z + base);
    float4 w = *(const float4*)(cw + tid * 4);
    float s = z.x * w.x + z.y * w.y + z.z * w.z + z.w * w.w;
#pragma unroll
    for (int o = 16; o > 0; o >>= 1) s += __shfl_xor_sync(0xffffffffu, s, o);
    if ((tid & 31) == 0) red[tid >> 5] = s;
    __syncthreads();
    float logit = red[0] + red[1] + red[2] + red[3] + cb[0];

    int full = 2 * B + B * D;
    if (out_size >= full) {
        if (tid == 0) {
            out[row]     = logit;
            out[B + row] = g_mask[row] ? 1.0f : 0.0f;
        }
        *(float4*)(out + 2 * B + base) = z;
        if (out_size > full) {
            for (int i = row * blockDim.x + tid; i < out_size - full;
                 i += gridDim.x * blockDim.x)
                out[full + i] = 0.0f;
        }
    } else if (out_size == B + B * D) {
        if (tid == 0) out[row] = logit;
        *(float4*)(out + B + base) = z;
    } else if (out_size == B * D) {
        *(float4*)(out + base) = z;
    } else {
        if (tid == 0 && row < out_size) out[row] = logit;
    }
}

// ---------------------------------------------------------------------------
extern "C" void kernel_launch(void* const* d_in, const int* in_sizes, int n_in,
                              void* d_out, int out_size)
{
    const float* z0   = (const float*)d_in[0];
    const float* ln1g = (const float*)d_in[1];
    const float* ln1b = (const float*)d_in[2];
    const float* w1   = (const float*)d_in[3];
    const float* b1   = (const float*)d_in[4];
    const float* w2   = (const float*)d_in[5];
    const float* b2   = (const float*)d_in[6];
    const float* ln2g = (const float*)d_in[7];
    const float* ln2b = (const float*)d_in[8];
    const float* w3   = (const float*)d_in[9];
    const float* b3   = (const float*)d_in[10];
    const float* w4   = (const float*)d_in[11];
    const float* b4   = (const float*)d_in[12];
    const float* cw   = (const float*)d_in[13];
    const float* cb   = (const float*)d_in[14];

    int D = in_sizes[1];          // 512
    int H = in_sizes[4];          // 2048
    int B = in_sizes[0] / D;      // 4096

    float *pz, *pu, *pxh, *pxl, *phh, *phl, *pw1, *pw2, *pw3, *pw4;
    cudaGetSymbolAddress((void**)&pz,  g_z);
    cudaGetSymbolAddress((void**)&pu,  g_u);
    cudaGetSymbolAddress((void**)&pxh, g_xh);
    cudaGetSymbolAddress((void**)&pxl, g_xl);
    cudaGetSymbolAddress((void**)&phh, g_hh);
    cudaGetSymbolAddress((void**)&phl, g_hl);
    cudaGetSymbolAddress((void**)&pw1, g_w1p);
    cudaGetSymbolAddress((void**)&pw2, g_w2p);
    cudaGetSymbolAddress((void**)&pw3, g_w3p);
    cudaGetSymbolAddress((void**)&pw4, g_w4p);

    const int SMEM_H = 3 * (4096 + 128 * 32) * 4;   // 98304 B
    const int SMEM_D = 3 * (4096 + 64 * 32) * 4;    // 73728 B
    cudaFuncSetAttribute(tgemm_kernel<128, 1>,
                         cudaFuncAttributeMaxDynamicSharedMemorySize, SMEM_H);
    cudaFuncSetAttribute(tgemm_kernel<64, 0>,
                         cudaFuncAttributeMaxDynamicSharedMemorySize, SMEM_D);

    // one-time weight packing (inside the graph; ~4 cheap launches)
    int totHD = (H / 8) * (D / 8) * 32;   // for W[D,H]: N=H, K=D
    int totDH = (D / 8) * (H / 8) * 32;   // same count
    pack_w_kernel<<<(totHD + 255) / 256, 256>>>(w1, pw1, D, H);
    pack_w_kernel<<<(totDH + 255) / 256, 256>>>(w2, pw2, H, D);
    pack_w_kernel<<<(totHD + 255) / 256, 256>>>(w3, pw3, D, H);
    pack_w_kernel<<<(totDH + 255) / 256, 256>>>(w4, pw4, H, D);

    int n = B * D;
    init_kernel<<<(n + 255) / 256, 256>>>(z0, n, B);

    dim3 gridH(H / 128, B / 128);   // 16 x 32 = 512 CTAs
    dim3 gridD(D / 64,  B / 128);   //  8 x 32 = 256 CTAs
    int  lnThreads = D / 4;         // 128

    for (int step = 0; step < NSTEPS; step++) {
        ln_pack_kernel<<<B / 16, 512>>>(pz, ln1g, ln1b, pxh, pxl, D);
        tgemm_kernel<128, 1><<<gridH, 256, SMEM_H>>>(pxh, pxl, pw1, b1, phh, phl, H, D);
        tgemm_kernel<64, 0><<<gridD, 256, SMEM_D>>>(phh, phl, pw2, b2, pu, nullptr, D, H);
        ln_pack_kernel<<<B / 16, 512>>>(pu, ln2g, ln2b, pxh, pxl, D);
        tgemm_kernel<128, 1><<<gridH, 256, SMEM_H>>>(pxh, pxl, pw3, b3, phh, phl, H, D);
        tgemm_kernel<64, 0><<<gridD, 256, SMEM_D>>>(phh, phl, pw4, b4, pu, nullptr, D, H);
        update_kernel<<<B, lnThreads>>>(D);
    }

    final_kernel<<<B, lnThreads>>>(cw, cb, (float*)d_out, B, D, out_size);
}

// round 9
// speedup vs baseline: 3.6246x; 1.7425x over previous
#include <cuda_runtime.h>
#include <cuda_fp16.h>
#include <math.h>
#include <stdint.h>

// ---------------------------------------------------------------------------
// TinyRecursiveVerifier — 3xFP16 split-precision mma.sync (m16n8k16).
//   a = ah + al_s * 2^-11 (lo scaled by 2048 -> stays fp16-normal).
//   C = (ah*bh) + (al_s*bh + ah*bl_s) * 2^-11, two fp32 accumulators.
//   All operands pre-packed fragment-major (weights once; activations by
//   producers). GEMM mainloop: cp.async (4-stage) -> LDS.128 -> MMA only.
// ---------------------------------------------------------------------------

#define MAXB 4096
#define MAXD 512
#define MAXH 2048
#define NSTEPS 32

__device__ float    g_z[MAXB * MAXD];
__device__ float    g_u[MAXB * MAXD];
__device__ unsigned g_mask[MAXB];
// packed fp16 fragment arrays (uint4 = one 32-lane tile's 16B/lane unit)
__device__ uint4 g_xh[MAXB * MAXD / 8];       // LN out hi
__device__ uint4 g_xl[MAXB * MAXD / 8];       // LN out lo (scaled)
__device__ uint4 g_hh[MAXB * MAXH / 8];       // hidden hi
__device__ uint4 g_hl[MAXB * MAXH / 8];       // hidden lo (scaled)
__device__ uint4 g_w1p[MAXD * MAXH / 4];      // weights: {b0h,b1h,b0l,b1l}
__device__ uint4 g_w2p[MAXH * MAXD / 4];
__device__ uint4 g_w3p[MAXD * MAXH / 4];
__device__ uint4 g_w4p[MAXH * MAXD / 4];

#define INV2048 4.8828125e-4f

__device__ __forceinline__ void split2(float v0, float v1, unsigned& hi, unsigned& lo) {
    __half h0 = __float2half_rn(v0), h1 = __float2half_rn(v1);
    float r0 = (v0 - __half2float(h0)) * 2048.0f;
    float r1 = (v1 - __half2float(h1)) * 2048.0f;
    __half2 hh = __halves2half2(h0, h1);
    __half2 ll = __floats2half2_rn(r0, r1);
    hi = *(unsigned*)&hh;
    lo = *(unsigned*)&ll;
}
__device__ __forceinline__ void mma16(float* c, const uint4& a,
                                      unsigned b0, unsigned b1) {
    asm volatile(
        "mma.sync.aligned.m16n8k16.row.col.f32.f16.f16.f32 "
        "{%0,%1,%2,%3}, {%4,%5,%6,%7}, {%8,%9}, {%0,%1,%2,%3};"
        : "+f"(c[0]), "+f"(c[1]), "+f"(c[2]), "+f"(c[3])
        : "r"(a.x), "r"(a.y), "r"(a.z), "r"(a.w), "r"(b0), "r"(b1));
}
__device__ __forceinline__ void cp16(uint32_t saddr, const void* gaddr) {
    asm volatile("cp.async.cg.shared.global [%0], [%1], 16;"
                 :: "r"(saddr), "l"(gaddr));
}
__device__ __forceinline__ float gelu_f(float x) {
    return 0.5f * x * (1.0f + erff(x * 0.70710678118654752440f));
}

// ---------------------------------------------------------------------------
// Weight pack: W[K,N] -> fragment-major fp16 hi/lo-scaled.
// Unit (nt, kt, lane): n = nt*8 + l>>2, k0 = kt*16 + 2*(l&3).
// uint4 = {h2(W[k0][n],W[k0+1][n]), h2(W[k0+8][n],W[k0+9][n]), lo0, lo1}.
// ---------------------------------------------------------------------------
__global__ void pack_w_kernel(const float* __restrict__ W, uint4* __restrict__ P,
                              int K, int N)
{
    int gid = blockIdx.x * 256 + threadIdx.x;
    int KT = K >> 4;
    int total = (N >> 3) * KT * 32;
    if (gid >= total) return;
    int ln = gid & 31, tile = gid >> 5;
    int kt = tile % KT, nt = tile / KT;
    int n  = nt * 8 + (ln >> 2);
    int k0 = kt * 16 + (ln & 3) * 2;
    float b00 = W[(size_t)k0 * N + n],       b01 = W[(size_t)(k0 + 1) * N + n];
    float b10 = W[(size_t)(k0 + 8) * N + n], b11 = W[(size_t)(k0 + 9) * N + n];
    uint4 o;
    split2(b00, b01, o.x, o.z);
    split2(b10, b11, o.y, o.w);
    P[gid] = o;
}

// ---------------------------------------------------------------------------
// LayerNorm + fragment pack. 16 rows/block, 512 threads (warp = row).
// Emits m16n8k16 A-fragments: unit (kt, lane): r = l>>2, k0 = kt*16+2*(l&3);
// uint4 = { (r,k0|k0+1), (r+8,...), (r,k0+8|k0+9), (r+8,...) } as half2s.
// ---------------------------------------------------------------------------
__global__ void ln_pack_kernel(const float* __restrict__ in,
                               const float* __restrict__ gam,
                               const float* __restrict__ bet,
                               uint4* __restrict__ out_hi,
                               uint4* __restrict__ out_lo, int D)
{
    __shared__ float y[16][516];
    const int tid  = threadIdx.x;
    const int w    = tid >> 5;
    const int lane = tid & 31;
    const int row  = blockIdx.x * 16 + w;
    const float* src = in + (size_t)row * D;
    const int J = D >> 7;                        // 4 for D=512

    float4 v[4];
    float s = 0.0f;
#pragma unroll
    for (int j = 0; j < 4; j++) {
        if (j < J) {
            v[j] = *(const float4*)(src + (lane + j * 32) * 4);
            s += v[j].x + v[j].y + v[j].z + v[j].w;
        }
    }
#pragma unroll
    for (int o = 16; o > 0; o >>= 1) s += __shfl_xor_sync(0xffffffffu, s, o);
    float mean = s / (float)D;

    float q = 0.0f;
#pragma unroll
    for (int j = 0; j < 4; j++) {
        if (j < J) {
            float a = v[j].x - mean, b = v[j].y - mean;
            float c = v[j].z - mean, d = v[j].w - mean;
            q += a * a + b * b + c * c + d * d;
        }
    }
#pragma unroll
    for (int o = 16; o > 0; o >>= 1) q += __shfl_xor_sync(0xffffffffu, q, o);
    float rstd = rsqrtf(q / (float)D + 1e-5f);

#pragma unroll
    for (int j = 0; j < 4; j++) {
        if (j < J) {
            int col = (lane + j * 32) * 4;
            float4 g4 = *(const float4*)(gam + col);
            float4 b4 = *(const float4*)(bet + col);
            float4 o;
            o.x = (v[j].x - mean) * rstd * g4.x + b4.x;
            o.y = (v[j].y - mean) * rstd * g4.y + b4.y;
            o.z = (v[j].z - mean) * rstd * g4.z + b4.z;
            o.w = (v[j].w - mean) * rstd * g4.w + b4.w;
            *(float4*)(&y[w][col]) = o;
        }
    }
    __syncthreads();

    const int KT = D >> 4;                       // 32
    for (int u = tid; u < KT * 32; u += 512) {
        int kt = u >> 5, ln = u & 31;
        int r = ln >> 2, k0 = kt * 16 + (ln & 3) * 2;
        uint4 hi, lo;
        split2(y[r][k0],         y[r][k0 + 1],     hi.x, lo.x);
        split2(y[r + 8][k0],     y[r + 8][k0 + 1], hi.y, lo.y);
        split2(y[r][k0 + 8],     y[r][k0 + 9],     hi.z, lo.z);
        split2(y[r + 8][k0 + 8], y[r + 8][k0 + 9], hi.w, lo.w);
        size_t base = ((size_t)blockIdx.x * KT + kt) * 32 + ln;
        out_hi[base] = hi;
        out_lo[base] = lo;
    }
}

// ---------------------------------------------------------------------------
// tgemm: C = epi(A @ B^T + bias). BM = 32*MT, BN = 64 (NT=2), BK=16.
// 8 warps (2m x 4n). 4-stage cp.async. Two accumulators (hh, cross).
// EPI=0: fp32 store (C0f). EPI=1: gelu + fragment-pack hi/lo (C0p/C1p) —
// the m16n8k16 A-fragment is exactly two adjacent m16n8 C tiles: NO shuffles.
// ---------------------------------------------------------------------------
template <int MT>
__device__ __forceinline__ void issue_chunk(
    uint32_t sb, const uint4* Ah, const uint4* Al, const uint4* Bp,
    int tid, int m0t, int n0t, int KT, int ch)
{
    constexpr int AUNITS = MT * 2 * 32;
    constexpr int AOFF   = AUNITS * 16;
    constexpr int BOFF   = 2 * AOFF;
    if (MT == 4 || tid < AUNITS) {
        int mt = tid >> 5, ln = tid & 31;
        size_t src = ((size_t)(m0t + mt) * KT + ch) * 32 + ln;
        cp16(sb + tid * 16, Ah + src);
        cp16(sb + AOFF + tid * 16, Al + src);
    }
    {
        int nt = tid >> 5, ln = tid & 31;
        size_t src = ((size_t)(n0t + nt) * KT + ch) * 32 + ln;
        cp16(sb + BOFF + tid * 16, Bp + src);
    }
}

template <int MT, int EPI>
__global__ __launch_bounds__(256, 2)
void tgemm_kernel(const uint4* __restrict__ Ah, const uint4* __restrict__ Al,
                  const uint4* __restrict__ Bp, const float* __restrict__ bias,
                  float* __restrict__ C0f, uint4* __restrict__ C0p,
                  uint4* __restrict__ C1p, int N, int K)
{
    constexpr int STAGES = 4;
    constexpr int AUNITS = MT * 2 * 32;
    constexpr int AOFF   = AUNITS * 16;          // bytes
    constexpr int BOFF   = 2 * AOFF;
    constexpr int SB     = BOFF + 256 * 16;      // stage bytes

    extern __shared__ uint4 S4[];
    const uint32_t sb0 = (uint32_t)__cvta_generic_to_shared(S4);
    const int tid  = threadIdx.x;
    const int wid  = tid >> 5;
    const int lane = tid & 31;
    const int wm   = wid >> 2;                   // 0..1
    const int wn   = wid & 3;                    // 0..3
    const int m0   = blockIdx.y * (32 * MT);
    const int n0   = blockIdx.x * 64;
    const int m0t  = m0 >> 4;
    const int n0t  = n0 >> 3;
    const int KT   = K >> 4;

    float acc0[MT][2][4], acc1[MT][2][4];
#pragma unroll
    for (int i = 0; i < MT; i++)
#pragma unroll
        for (int j = 0; j < 2; j++)
#pragma unroll
            for (int t = 0; t < 4; t++) { acc0[i][j][t] = 0.0f; acc1[i][j][t] = 0.0f; }

#pragma unroll
    for (int s = 0; s < STAGES - 1; s++) {
        issue_chunk<MT>(sb0 + s * SB, Ah, Al, Bp, tid, m0t, n0t, KT, s);
        asm volatile("cp.async.commit_group;");
    }

    for (int ch = 0; ch < KT; ch++) {
        asm volatile("cp.async.wait_group %0;" :: "n"(STAGES - 2));
        __syncthreads();
        int nx = ch + STAGES - 1;
        if (nx < KT)
            issue_chunk<MT>(sb0 + (nx % STAGES) * SB, Ah, Al, Bp, tid,
                            m0t, n0t, KT, nx);
        asm volatile("cp.async.commit_group;");

        const uint4* buf = S4 + (ch % STAGES) * (SB / 16);
        const uint4* As  = buf;
        const uint4* Ls  = buf + AOFF / 16;
        const uint4* Bs  = buf + BOFF / 16;
        uint4 ah[MT], al[MT], bb[2];
#pragma unroll
        for (int i = 0; i < MT; i++) {
            int grp = (wm * MT + i) * 32 + lane;
            ah[i] = As[grp];
            al[i] = Ls[grp];
        }
#pragma unroll
        for (int j = 0; j < 2; j++)
            bb[j] = Bs[(wn * 2 + j) * 32 + lane];
#pragma unroll
        for (int i = 0; i < MT; i++)
#pragma unroll
            for (int j = 0; j < 2; j++) {
                mma16(acc0[i][j], ah[i], bb[j].x, bb[j].y);  // hi*hi
                mma16(acc1[i][j], al[i], bb[j].x, bb[j].y);  // lo_s*hi
                mma16(acc1[i][j], ah[i], bb[j].z, bb[j].w);  // hi*lo_s
            }
    }

    // ---- epilogue ----
    const int grp = lane >> 2, t = lane & 3;
    if (EPI == 0) {
#pragma unroll
        for (int i = 0; i < MT; i++) {
            int row0 = m0 + wm * MT * 16 + i * 16 + grp;
#pragma unroll
            for (int j = 0; j < 2; j++) {
                int col = n0 + wn * 16 + j * 8 + 2 * t;
                float b0 = bias[col], b1 = bias[col + 1];
                float2 v0, v1;
                v0.x = acc0[i][j][0] + acc1[i][j][0] * INV2048 + b0;
                v0.y = acc0[i][j][1] + acc1[i][j][1] * INV2048 + b1;
                v1.x = acc0[i][j][2] + acc1[i][j][2] * INV2048 + b0;
                v1.y = acc0[i][j][3] + acc1[i][j][3] * INV2048 + b1;
                *(float2*)(C0f + (size_t)row0 * N + col)       = v0;
                *(float2*)(C0f + (size_t)(row0 + 8) * N + col) = v1;
            }
        }
    } else {
        const int KTO = N >> 4;
        const int C0c = n0 + wn * 16;
#pragma unroll
        for (int i = 0; i < MT; i++) {
            int R0 = m0 + wm * MT * 16 + i * 16;
            float g[8];
#pragma unroll
            for (int j = 0; j < 2; j++) {
                int col = C0c + j * 8 + 2 * t;
                float b0 = bias[col], b1 = bias[col + 1];
                g[j * 4 + 0] = gelu_f(acc0[i][j][0] + acc1[i][j][0] * INV2048 + b0);
                g[j * 4 + 1] = gelu_f(acc0[i][j][1] + acc1[i][j][1] * INV2048 + b1);
                g[j * 4 + 2] = gelu_f(acc0[i][j][2] + acc1[i][j][2] * INV2048 + b0);
                g[j * 4 + 3] = gelu_f(acc0[i][j][3] + acc1[i][j][3] * INV2048 + b1);
            }
            uint4 hi, lo;
            split2(g[0], g[1], hi.x, lo.x);   // (r,   k0|k0+1)  <- j0 c0,c1
            split2(g[2], g[3], hi.y, lo.y);   // (r+8, k0|k0+1)  <- j0 c2,c3
            split2(g[4], g[5], hi.z, lo.z);   // (r,   k0+8|+9)  <- j1 c0,c1
            split2(g[6], g[7], hi.w, lo.w);   // (r+8, k0+8|+9)  <- j1 c2,c3
            size_t base = ((size_t)(R0 >> 4) * KTO + (C0c >> 4)) * 32 + lane;
            C0p[base] = hi;
            C1p[base] = lo;
        }
    }
}

// ---------------------------------------------------------------------------
__global__ void update_kernel(int D)
{
    int row = blockIdx.x, tid = threadIdx.x;
    __shared__ float red[4];
    size_t base = (size_t)row * D + tid * 4;
    float4 d = *(const float4*)(g_u + base);
    float q = d.x * d.x + d.y * d.y + d.z * d.z + d.w * d.w;
#pragma unroll
    for (int o = 16; o > 0; o >>= 1) q += __shfl_xor_sync(0xffffffffu, q, o);
    if ((tid & 31) == 0) red[tid >> 5] = q;
    __syncthreads();
    float ss = red[0] + red[1] + red[2] + red[3];

    unsigned conv = (g_mask[row] != 0u) || (sqrtf(ss) < 0.01f);
    if (!conv) {
        float4 z = *(const float4*)(g_z + base);
        z.x += d.x; z.y += d.y; z.z += d.z; z.w += d.w;
        *(float4*)(g_z + base) = z;
    }
    if (tid == 0) g_mask[row] = conv ? 1u : 0u;
}

__global__ void init_kernel(const float* __restrict__ z0, int n, int Bn)
{
    int i = blockIdx.x * blockDim.x + threadIdx.x;
    if (i < n)  g_z[i]    = z0[i];
    if (i < Bn) g_mask[i] = 0u;
}

__global__ void final_kernel(const float* __restrict__ cw, const float* __restrict__ cb,
                             float* __restrict__ out, int B, int D, int out_size)
{
    int row = blockIdx.x, tid = threadIdx.x;
    __shared__ float red[4];
    size_t base = (size_t)row * D + tid * 4;
    float4 z = *(const float4*)(g_z + base);
    float4 w = *(const float4*)(cw + tid * 4);
    float s = z.x * w.x + z.y * w.y + z.z * w.z + z.w * w.w;
#pragma unroll
    for (int o = 16; o > 0; o >>= 1) s += __shfl_xor_sync(0xffffffffu, s, o);
    if ((tid & 31) == 0) red[tid >> 5] = s;
    __syncthreads();
    float logit = red[0] + red[1] + red[2] + red[3] + cb[0];

    int full = 2 * B + B * D;
    if (out_size >= full) {
        if (tid == 0) {
            out[row]     = logit;
            out[B + row] = g_mask[row] ? 1.0f : 0.0f;
        }
        *(float4*)(out + 2 * B + base) = z;
        if (out_size > full) {
            for (int i = row * blockDim.x + tid; i < out_size - full;
                 i += gridDim.x * blockDim.x)
                out[full + i] = 0.0f;
        }
    } else if (out_size == B + B * D) {
        if (tid == 0) out[row] = logit;
        *(float4*)(out + B + base) = z;
    } else if (out_size == B * D) {
        *(float4*)(out + base) = z;
    } else {
        if (tid == 0 && row < out_size) out[row] = logit;
    }
}

// ---------------------------------------------------------------------------
extern "C" void kernel_launch(void* const* d_in, const int* in_sizes, int n_in,
                              void* d_out, int out_size)
{
    const float* z0   = (const float*)d_in[0];
    const float* ln1g = (const float*)d_in[1];
    const float* ln1b = (const float*)d_in[2];
    const float* w1   = (const float*)d_in[3];
    const float* b1   = (const float*)d_in[4];
    const float* w2   = (const float*)d_in[5];
    const float* b2   = (const float*)d_in[6];
    const float* ln2g = (const float*)d_in[7];
    const float* ln2b = (const float*)d_in[8];
    const float* w3   = (const float*)d_in[9];
    const float* b3   = (const float*)d_in[10];
    const float* w4   = (const float*)d_in[11];
    const float* b4   = (const float*)d_in[12];
    const float* cw   = (const float*)d_in[13];
    const float* cb   = (const float*)d_in[14];

    int D = in_sizes[1];          // 512
    int H = in_sizes[4];          // 2048
    int B = in_sizes[0] / D;      // 4096

    float *pz, *pu;
    uint4 *pxh, *pxl, *phh, *phl, *pw1, *pw2, *pw3, *pw4;
    cudaGetSymbolAddress((void**)&pz,  g_z);
    cudaGetSymbolAddress((void**)&pu,  g_u);
    cudaGetSymbolAddress((void**)&pxh, g_xh);
    cudaGetSymbolAddress((void**)&pxl, g_xl);
    cudaGetSymbolAddress((void**)&phh, g_hh);
    cudaGetSymbolAddress((void**)&phl, g_hl);
    cudaGetSymbolAddress((void**)&pw1, g_w1p);
    cudaGetSymbolAddress((void**)&pw2, g_w2p);
    cudaGetSymbolAddress((void**)&pw3, g_w3p);
    cudaGetSymbolAddress((void**)&pw4, g_w4p);

    const int SMH = 4 * (2 * 256 * 16 + 256 * 16);   // MT=4: 49152 B
    const int SMD = 4 * (2 * 128 * 16 + 256 * 16);   // MT=2: 32768 B
    cudaFuncSetAttribute(tgemm_kernel<4, 1>,
                         cudaFuncAttributeMaxDynamicSharedMemorySize, SMH);
    cudaFuncSetAttribute(tgemm_kernel<2, 0>,
                         cudaFuncAttributeMaxDynamicSharedMemorySize, SMD);

    // one-time weight packing
    int totHD = (H / 8) * (D / 16) * 32;
    int totDH = (D / 8) * (H / 16) * 32;
    pack_w_kernel<<<(totHD + 255) / 256, 256>>>(w1, pw1, D, H);
    pack_w_kernel<<<(totDH + 255) / 256, 256>>>(w2, pw2, H, D);
    pack_w_kernel<<<(totHD + 255) / 256, 256>>>(w3, pw3, D, H);
    pack_w_kernel<<<(totDH + 255) / 256, 256>>>(w4, pw4, H, D);

    int n = B * D;
    init_kernel<<<(n + 255) / 256, 256>>>(z0, n, B);

    dim3 gridH(H / 64, B / 128);    // 32 x 32 = 1024 CTAs
    dim3 gridD(D / 64, B / 64);     //  8 x 64 =  512 CTAs

    for (int step = 0; step < NSTEPS; step++) {
        ln_pack_kernel<<<B / 16, 512>>>(pz, ln1g, ln1b, pxh, pxl, D);
        tgemm_kernel<4, 1><<<gridH, 256, SMH>>>(pxh, pxl, pw1, b1,
                                                nullptr, phh, phl, H, D);
        tgemm_kernel<2, 0><<<gridD, 256, SMD>>>(phh, phl, pw2, b2,
                                                pu, nullptr, nullptr, D, H);
        ln_pack_kernel<<<B / 16, 512>>>(pu, ln2g, ln2b, pxh, pxl, D);
        tgemm_kernel<4, 1><<<gridH, 256, SMH>>>(pxh, pxl, pw3, b3,
                                                nullptr, phh, phl, H, D);
        tgemm_kernel<2, 0><<<gridD, 256, SMD>>>(phh, phl, pw4, b4,
                                                pu, nullptr, nullptr, D, H);
        update_kernel<<<B, D / 4>>>(D);
    }

    final_kernel<<<B, D / 4>>>(cw, cb, (float*)d_out, B, D, out_size);
}